// round 16
// baseline (speedup 1.0000x reference)
#include <cuda_runtime.h>
#include <cuda_bf16.h>
#include <cstdint>
#define DEV __device__ __forceinline__
typedef unsigned long long ull;

__device__ float         g_hs[8192*128];
__device__ float         g_hn[8192*128];
__device__ __nv_bfloat16 g_hnB[8192*128];   // bf16 h_n, row-major [j][f]
__device__ uint32_t      g_adjB[8192*256];  // bit-packed adj
__device__ float         g_Es[8192], g_En[8192];
__device__ float         g_part[256*128*128];
__device__ float         g_den[256*128];

DEV uint32_t smem_u32(const void* p){uint32_t a;asm("{ .reg .u64 t; cvta.to.shared.u64 t, %1; cvt.u32.u64 %0, t; }":"=r"(a):"l"(p));return a;}
DEV uint32_t packbf(float lo,float hi){uint32_t r;asm("cvt.rn.bf16x2.f32 %0, %1, %2;":"=r"(r):"f"(hi),"f"(lo));return r;}
#define FMA2(d,a,b,c) asm("fma.rn.f32x2 %0, %1, %2, %3;":"=l"(d):"l"(a),"l"(b),"l"(c))
DEV ull pack2(float x,float y){ull d;asm("mov.b64 %0, {%1, %2};":"=l"(d):"f"(x),"f"(y));return d;}
DEV void unpack2(ull d,float&x,float&y){asm("mov.b64 {%0, %1}, %2;":"=f"(x),"=f"(y):"l"(d));}
DEV void cp16(uint32_t dst, const void* src){asm volatile("cp.async.ca.shared.global [%0], [%1], 16;"::"r"(dst),"l"(src):"memory");}
#define CP_COMMIT() asm volatile("cp.async.commit_group;":::"memory")
#define CP_WAIT0()  asm volatile("cp.async.wait_group 0;":::"memory")
DEV void ldsm4t(uint32_t& r0,uint32_t& r1,uint32_t& r2,uint32_t& r3,uint32_t a){
  asm volatile("ldmatrix.sync.aligned.m8n8.x4.trans.shared.b16 {%0,%1,%2,%3}, [%4];"
               :"=r"(r0),"=r"(r1),"=r"(r2),"=r"(r3):"r"(a));}
DEV void mma16816(float& c0,float& c1,float& c2,float& c3,
                  uint32_t a0,uint32_t a1,uint32_t a2,uint32_t a3,uint32_t b0,uint32_t b1){
  asm volatile("mma.sync.aligned.m16n8k16.row.col.f32.bf16.bf16.f32 "
               "{%0,%1,%2,%3},{%4,%5,%6,%7},{%8,%9},{%0,%1,%2,%3};"
               :"+f"(c0),"+f"(c1),"+f"(c2),"+f"(c3)
               :"r"(a0),"r"(a1),"r"(a2),"r"(a3),"r"(b0),"r"(b1));}

// ---- fused pre-pass: blocks [0,8192) bit-pack adj; blocks [8192,8320) projections ----
__global__ void __launch_bounds__(256) k_pre(const int* __restrict__ adj,
                                             const float* __restrict__ X,
                                             const float* __restrict__ Ws,
                                             const float* __restrict__ Wn){
  __shared__ float sX[32][136], sW[32][128];
  if (blockIdx.x < 8192){
    // ---- prebit: one adj row per block ----
    int row = blockIdx.x;
    const int* ap = adj + (size_t)row*8192;
    int lane = threadIdx.x & 31, w = threadIdx.x >> 5;
    uint32_t* dst = g_adjB + (size_t)row*256 + w;
#pragma unroll 4
    for (int it=0; it<32; ++it){
      int v = ap[it*256 + threadIdx.x];
      uint32_t word = __ballot_sync(0xffffffffu, v>0);
      if (lane==0) dst[it*8] = word;
    }
    return;
  }
  // ---- projection: 128x128 out tile, K=256 ----
  int pid = blockIdx.x - 8192;
  const float* W = (pid>>6) ? Wn : Ws;
  float* H = (pid>>6) ? g_hn : g_hs;
  int r0 = (pid&63)*128;
  int tr = threadIdx.x>>4, tc = threadIdx.x&15;
  ull acc[8][4] = {};
  for (int k0=0; k0<256; k0+=32){
    __syncthreads();
    for (int idx=threadIdx.x; idx<128*32; idx+=256){
      int r=idx>>5, k=idx&31;
      sX[k][r] = X[(size_t)(r0+r)*256 + k0 + k];
    }
    { int idx=threadIdx.x; int k=idx>>3, c4=(idx&7)*16;
      float4 v0=*(const float4*)(W+(size_t)(k0+k)*128+c4);
      float4 v1=*(const float4*)(W+(size_t)(k0+k)*128+c4+4);
      float4 v2=*(const float4*)(W+(size_t)(k0+k)*128+c4+8);
      float4 v3=*(const float4*)(W+(size_t)(k0+k)*128+c4+12);
      *(float4*)&sW[k][c4]=v0; *(float4*)&sW[k][c4+4]=v1;
      *(float4*)&sW[k][c4+8]=v2; *(float4*)&sW[k][c4+12]=v3;
    }
    __syncthreads();
    for (int k=0;k<32;++k){
      ull wv[4]; float xv[8];
#pragma unroll
      for (int p=0;p<4;++p) wv[p] = *(const ull*)&sW[k][tc*8+2*p];
#pragma unroll
      for (int q=0;q<8;++q) xv[q] = sX[k][tr*8+q];
#pragma unroll
      for (int q=0;q<8;++q){ ull xp = pack2(xv[q],xv[q]);
#pragma unroll
        for (int p=0;p<4;++p) FMA2(acc[q][p], xp, wv[p], acc[q][p]); }
    }
  }
#pragma unroll
  for (int q=0;q<8;++q){
    float o[8];
#pragma unroll
    for (int p=0;p<4;++p) unpack2(acc[q][p], o[2*p], o[2*p+1]);
    float* dst = H + (size_t)(r0+tr*8+q)*128 + tc*8;
    *(float4*)dst = make_float4(o[0],o[1],o[2],o[3]);
    *(float4*)(dst+4) = make_float4(o[4],o[5],o[6],o[7]);
  }
}

// ---- dots + bf16 copy: grid 64, block 128 ----
__global__ void __launch_bounds__(128) k_dots(const float* __restrict__ av_s,
                                              const float* __restrict__ av_n){
  __shared__ float sA[128], sB[128];
  int tid = threadIdx.x;
  sA[tid]=av_s[tid]; sB[tid]=av_n[tid];
  __syncthreads();
  int j = blockIdx.x*128 + tid;
  const float4* hs4=(const float4*)(g_hs+(size_t)j*128);
  const float4* hn4=(const float4*)(g_hn+(size_t)j*128);
  uint2* dst=(uint2*)(g_hnB+(size_t)j*128);
  float s=0.f,n=0.f;
#pragma unroll 8
  for (int q=0;q<32;++q){
    float4 a=hs4[q];
    s += a.x*sA[4*q]+a.y*sA[4*q+1]+a.z*sA[4*q+2]+a.w*sA[4*q+3];
    float4 b=hn4[q];
    n += b.x*sB[4*q]+b.y*sB[4*q+1]+b.z*sB[4*q+2]+b.w*sB[4*q+3];
    uint2 u; u.x=packbf(b.x,b.y); u.y=packbf(b.z,b.w);
    dst[q]=u;
  }
  g_Es[j]=expf(s); g_En[j]=expf(n);
}

// ---- main contraction: bit-adj + smem/ldsm B pipeline (R10, measured 71.4us) ----
__global__ void __launch_bounds__(256,2) k_attn(){
  __shared__ __align__(16) char bsm[2][16*272];
  int tid=threadIdx.x, lane=tid&31, w=tid>>5;
  int it=blockIdx.x>>2, quarter=blockIdx.x&3;
  int i0=it*128, jb=quarter*2048;
  uint32_t ba[2]={smem_u32(&bsm[0][0]),smem_u32(&bsm[1][0])};

  int r0=lane>>2, cq=(lane&3)*2;
  int gr0=i0+w*16+r0, gr1=gr0+8;
  const uint32_t* wrow0=g_adjB+(size_t)gr0*256+(jb>>5);
  const uint32_t* wrow1=g_adjB+(size_t)gr1*256+(jb>>5);
  const float* enp=g_En+jb+cq;
  float es0=g_Es[gr0], es1=g_Es[gr1];

  int lk=(lane<16)?lane:(lane-16);
  int ln8=(lane<16)?0:8;
  uint32_t lmoff=(uint32_t)lk*272u+(uint32_t)ln8*2u;

  int brow=tid>>4, bcol=(tid&15)*8;
  uint32_t bo=(uint32_t)brow*272u+(uint32_t)bcol*2u;
  const __nv_bfloat16* bs=g_hnB+(size_t)(jb+brow)*128+bcol;

  float acc[16][4]={};
  float dacc0=0.f, dacc1=0.f;

  cp16(ba[0]+bo, bs); CP_COMMIT();    // B chunk 0

  uint32_t W0=wrow0[0], W1=wrow1[0];
  float2 E[4]={ *(const float2*)(enp), *(const float2*)(enp+8),
                *(const float2*)(enp+16), *(const float2*)(enp+24) };

  for (int s=0;s<64;++s){
    int sn=(s+1<64)?(s+1):63;
    uint32_t nW0=wrow0[sn], nW1=wrow1[sn];
    const float* ep=enp+sn*32;
    float2 nE0=*(const float2*)(ep),    nE1=*(const float2*)(ep+8);
    float2 nE2=*(const float2*)(ep+16), nE3=*(const float2*)(ep+24);

#pragma unroll
    for (int h=0;h<2;++h){
      int c=2*s+h;
      CP_WAIT0();
      __syncthreads();
      if (c+1<128) cp16(ba[(c+1)&1]+bo, bs+(size_t)(c+1)*16*128);
      CP_COMMIT();

      int sh=h*16;
      float2 E0=E[2*h], E1=E[2*h+1];
      float w00=((W0>>(sh+cq  ))&1)?fmaxf(es0*E0.x,1.f):0.f;
      float w01=((W0>>(sh+cq+1))&1)?fmaxf(es0*E0.y,1.f):0.f;
      float w10=((W1>>(sh+cq  ))&1)?fmaxf(es1*E0.x,1.f):0.f;
      float w11=((W1>>(sh+cq+1))&1)?fmaxf(es1*E0.y,1.f):0.f;
      float w02=((W0>>(sh+cq+8))&1)?fmaxf(es0*E1.x,1.f):0.f;
      float w03=((W0>>(sh+cq+9))&1)?fmaxf(es0*E1.y,1.f):0.f;
      float w12=((W1>>(sh+cq+8))&1)?fmaxf(es1*E1.x,1.f):0.f;
      float w13=((W1>>(sh+cq+9))&1)?fmaxf(es1*E1.y,1.f):0.f;
      dacc0 += (w00+w01)+(w02+w03);
      dacc1 += (w10+w11)+(w12+w13);
      uint32_t a0=packbf(w00,w01), a1=packbf(w10,w11), a2=packbf(w02,w03), a3=packbf(w12,w13);

      uint32_t bbase=ba[c&1]+lmoff;
#pragma unroll
      for (int nt2=0;nt2<8;++nt2){
        uint32_t q0,q1,q2,q3;
        ldsm4t(q0,q1,q2,q3, bbase+(uint32_t)nt2*32u);
        mma16816(acc[2*nt2][0],acc[2*nt2][1],acc[2*nt2][2],acc[2*nt2][3],       a0,a1,a2,a3, q0,q1);
        mma16816(acc[2*nt2+1][0],acc[2*nt2+1][1],acc[2*nt2+1][2],acc[2*nt2+1][3],a0,a1,a2,a3, q2,q3);
      }
    }
    W0=nW0; W1=nW1; E[0]=nE0; E[1]=nE1; E[2]=nE2; E[3]=nE3;
  }

  dacc0 += __shfl_xor_sync(0xffffffffu,dacc0,1);
  dacc0 += __shfl_xor_sync(0xffffffffu,dacc0,2);
  dacc1 += __shfl_xor_sync(0xffffffffu,dacc1,1);
  dacc1 += __shfl_xor_sync(0xffffffffu,dacc1,2);
  if ((lane&3)==0){
    g_den[blockIdx.x*128 + w*16 + r0]     = dacc0;
    g_den[blockIdx.x*128 + w*16 + r0 + 8] = dacc1;
  }
  float* gp0=g_part+((size_t)blockIdx.x*128 + w*16 + r0)*128 + cq;
  float* gp1=gp0 + (size_t)8*128;
#pragma unroll
  for (int nt=0;nt<16;++nt){
    *(float2*)(gp0+nt*8)=make_float2(acc[nt][0],acc[nt][1]);
    *(float2*)(gp1+nt*8)=make_float2(acc[nt][2],acc[nt][3]);
  }
}

// ---- epilogue: grid 1024, block 256 ----
__global__ void __launch_bounds__(256) k_epi(float* __restrict__ out){
  int t=blockIdx.x*256+threadIdx.x;
  int i=t>>5, fq=(t&31)*4;
  int it=i>>7, li=i&127;
  size_t pb=(((size_t)it*4)*128+li)*128+fq;
  float4 n0=*(const float4*)(g_part+pb);
  float4 n1=*(const float4*)(g_part+pb+128*128);
  float4 n2=*(const float4*)(g_part+pb+2*128*128);
  float4 n3=*(const float4*)(g_part+pb+3*128*128);
  int db=it*512+li;
  float den=g_den[db]+g_den[db+128]+g_den[db+256]+g_den[db+384];
  float4 hs=*(const float4*)(g_hs+(size_t)i*128+fq);
  float4 v;
  v.x=0.5f*hs.x+(n0.x+n1.x+n2.x+n3.x)/den;
  v.y=0.5f*hs.y+(n0.y+n1.y+n2.y+n3.y)/den;
  v.z=0.5f*hs.z+(n0.z+n1.z+n2.z+n3.z)/den;
  v.w=0.5f*hs.w+(n0.w+n1.w+n2.w+n3.w)/den;
  v.x = v.x>0.f ? v.x : expm1f(v.x);
  v.y = v.y>0.f ? v.y : expm1f(v.y);
  v.z = v.z>0.f ? v.z : expm1f(v.z);
  v.w = v.w>0.f ? v.w : expm1f(v.w);
  *(float4*)(out+(size_t)i*128+fq)=v;
}

extern "C" void kernel_launch(void* const* d_in, const int* in_sizes, int n_in,
                              void* d_out, int out_size){
  const float* X  =(const float*)d_in[0];
  const int*   adj=(const int*)d_in[1];
  const float* Ws =(const float*)d_in[2];
  const float* as_=(const float*)d_in[3];
  const float* Wn =(const float*)d_in[4];
  const float* an_=(const float*)d_in[5];
  k_pre<<<8320,256>>>(adj, X, Ws, Wn);
  k_dots<<<64,128>>>(as_, an_);
  k_attn<<<256,256>>>();
  k_epi<<<1024,256>>>((float*)d_out);
}

// round 17
// speedup vs baseline: 1.9590x; 1.9590x over previous
#include <cuda_runtime.h>
#include <cuda_bf16.h>
#include <cstdint>
#define DEV __device__ __forceinline__
typedef unsigned long long ull;

__device__ float         g_hs[8192*128];
__device__ float         g_hn[8192*128];
__device__ __nv_bfloat16 g_hnB[8192*128];   // bf16 h_n, row-major [j][f]
__device__ float         g_Es[8192], g_En[8192];
__device__ float         g_part[256*128*128];
__device__ float         g_den[256*128];

DEV uint32_t smem_u32(const void* p){uint32_t a;asm("{ .reg .u64 t; cvta.to.shared.u64 t, %1; cvt.u32.u64 %0, t; }":"=r"(a):"l"(p));return a;}
DEV uint32_t packbf(float lo,float hi){uint32_t r;asm("cvt.rn.bf16x2.f32 %0, %1, %2;":"=r"(r):"f"(hi),"f"(lo));return r;}
#define FMA2(d,a,b,c) asm("fma.rn.f32x2 %0, %1, %2, %3;":"=l"(d):"l"(a),"l"(b),"l"(c))
DEV ull pack2(float x,float y){ull d;asm("mov.b64 %0, {%1, %2};":"=l"(d):"f"(x),"f"(y));return d;}
DEV void unpack2(ull d,float&x,float&y){asm("mov.b64 {%0, %1}, %2;":"=f"(x),"=f"(y):"l"(d));}
DEV void cp16cg(uint32_t dst, const void* src){asm volatile("cp.async.cg.shared.global [%0], [%1], 16;"::"r"(dst),"l"(src):"memory");}
#define CP_COMMIT() asm volatile("cp.async.commit_group;":::"memory")
#define CP_WAIT2()  asm volatile("cp.async.wait_group 2;":::"memory")
DEV void ldsm4t(uint32_t& r0,uint32_t& r1,uint32_t& r2,uint32_t& r3,uint32_t a){
  asm volatile("ldmatrix.sync.aligned.m8n8.x4.trans.shared.b16 {%0,%1,%2,%3}, [%4];"
               :"=r"(r0),"=r"(r1),"=r"(r2),"=r"(r3):"r"(a));}
DEV void mma16816(float& c0,float& c1,float& c2,float& c3,
                  uint32_t a0,uint32_t a1,uint32_t a2,uint32_t a3,uint32_t b0,uint32_t b1){
  asm volatile("mma.sync.aligned.m16n8k16.row.col.f32.bf16.bf16.f32 "
               "{%0,%1,%2,%3},{%4,%5,%6,%7},{%8,%9},{%0,%1,%2,%3};"
               :"+f"(c0),"+f"(c1),"+f"(c2),"+f"(c3)
               :"r"(a0),"r"(a1),"r"(a2),"r"(a3),"r"(b0),"r"(b1));}

// ---- projections + fused dots/exp/bf16: grid (64,2), block 256 ----
__global__ void __launch_bounds__(256) k_proj(const float* __restrict__ X,
                                              const float* __restrict__ Ws,
                                              const float* __restrict__ Wn,
                                              const float* __restrict__ av_s,
                                              const float* __restrict__ av_n){
  __shared__ float sX[32][136], sW[32][128];
  __shared__ float sAv[128];
  const float* W = blockIdx.y ? Wn : Ws;
  float* H = blockIdx.y ? g_hn : g_hs;
  const float* av = blockIdx.y ? av_n : av_s;
  if (threadIdx.x < 128) sAv[threadIdx.x] = av[threadIdx.x];
  int r0 = blockIdx.x*128;
  int tr = threadIdx.x>>4, tc = threadIdx.x&15;
  ull acc[8][4] = {};
  for (int k0=0; k0<256; k0+=32){
    __syncthreads();
    for (int idx=threadIdx.x; idx<128*32; idx+=256){
      int r=idx>>5, k=idx&31;
      sX[k][r] = X[(size_t)(r0+r)*256 + k0 + k];
    }
    { int idx=threadIdx.x; int k=idx>>3, c4=(idx&7)*16;
      float4 v0=*(const float4*)(W+(size_t)(k0+k)*128+c4);
      float4 v1=*(const float4*)(W+(size_t)(k0+k)*128+c4+4);
      float4 v2=*(const float4*)(W+(size_t)(k0+k)*128+c4+8);
      float4 v3=*(const float4*)(W+(size_t)(k0+k)*128+c4+12);
      *(float4*)&sW[k][c4]=v0; *(float4*)&sW[k][c4+4]=v1;
      *(float4*)&sW[k][c4+8]=v2; *(float4*)&sW[k][c4+12]=v3;
    }
    __syncthreads();
    for (int k=0;k<32;++k){
      ull wv[4]; float xv[8];
#pragma unroll
      for (int p=0;p<4;++p) wv[p] = *(const ull*)&sW[k][tc*8+2*p];
#pragma unroll
      for (int q=0;q<8;++q) xv[q] = sX[k][tr*8+q];
#pragma unroll
      for (int q=0;q<8;++q){ ull xp = pack2(xv[q],xv[q]);
#pragma unroll
        for (int p=0;p<4;++p) FMA2(acc[q][p], xp, wv[p], acc[q][p]); }
    }
  }
  float a0=sAv[tc*8],   a1=sAv[tc*8+1], a2=sAv[tc*8+2], a3=sAv[tc*8+3];
  float a4=sAv[tc*8+4], a5=sAv[tc*8+5], a6=sAv[tc*8+6], a7=sAv[tc*8+7];
#pragma unroll
  for (int q=0;q<8;++q){
    int row = r0+tr*8+q;
    float o[8];
#pragma unroll
    for (int p=0;p<4;++p) unpack2(acc[q][p], o[2*p], o[2*p+1]);
    float* dst = H + (size_t)row*128 + tc*8;
    *(float4*)dst = make_float4(o[0],o[1],o[2],o[3]);
    *(float4*)(dst+4) = make_float4(o[4],o[5],o[6],o[7]);
    if (blockIdx.y){    // bf16 copy of h_n
      uint2* bd=(uint2*)(g_hnB+(size_t)row*128+tc*8);
      bd[0]=make_uint2(packbf(o[0],o[1]),packbf(o[2],o[3]));
      bd[1]=make_uint2(packbf(o[4],o[5]),packbf(o[6],o[7]));
    }
    // row-dot with av: partial over this thread's 8 cols, reduce over tc (lane%16)
    float d = o[0]*a0+o[1]*a1+o[2]*a2+o[3]*a3+o[4]*a4+o[5]*a5+o[6]*a6+o[7]*a7;
    d += __shfl_xor_sync(0xffffffffu,d,1);
    d += __shfl_xor_sync(0xffffffffu,d,2);
    d += __shfl_xor_sync(0xffffffffu,d,4);
    d += __shfl_xor_sync(0xffffffffu,d,8);
    if (tc==0){
      float e = expf(d);
      if (blockIdx.y) g_En[row]=e; else g_Es[row]=e;
    }
  }
}

// ---- main contraction: adj streamed via cp.async.cg, 4-stage ring (R13, verbatim) ----
#define STG_STRIDE 27136
#define B_OFF      18432
#define SMEM_TOTAL (4*STG_STRIDE)
__global__ void __launch_bounds__(256,2) k_attn(const int* __restrict__ adj){
  extern __shared__ __align__(16) char smc[];
  uint32_t sb = smem_u32(smc);
  int tid=threadIdx.x, lane=tid&31, w=tid>>5;
  int it=blockIdx.x>>2, quarter=blockIdx.x&3;
  int i0=it*128, jb=quarter*2048;

  int r0=lane>>2, cq=(lane&3)*2;
  int gr0=i0+w*16+r0, gr1=gr0+8;
  const float* enp=g_En+jb+cq;
  float es0=g_Es[gr0], es1=g_Es[gr1];

  int lk=(lane<16)?lane:(lane-16);
  int ln8=(lane<16)?0:8;
  uint32_t lmoff=(uint32_t)lk*272u+(uint32_t)ln8*2u;

  uint32_t aoff[4]; const int* asrc[4];
  uint32_t boff[2]; const __nv_bfloat16* bsrc[2];
#pragma unroll
  for (int q=0;q<4;++q){
    int idx=q*256+tid, row=idx>>3, seg=idx&7;
    aoff[q]=(uint32_t)row*144u+(uint32_t)seg*16u;
    asrc[q]=adj+(size_t)(i0+row)*8192+jb+seg*4;
  }
#pragma unroll
  for (int q=0;q<2;++q){
    int idx=q*256+tid, brow=idx>>4, bseg=idx&15;
    boff[q]=(uint32_t)(B_OFF+brow*272+bseg*16);
    bsrc[q]=g_hnB+(size_t)(jb+brow)*128+bseg*8;
  }

#pragma unroll
  for (int s2=0;s2<3;++s2){
    uint32_t st=sb+(uint32_t)s2*STG_STRIDE;
#pragma unroll
    for (int q=0;q<4;++q) cp16cg(st+aoff[q], asrc[q]+s2*32);
#pragma unroll
    for (int q=0;q<2;++q) cp16cg(st+boff[q], bsrc[q]+(size_t)s2*32*128);
    CP_COMMIT();
  }

  float acc[16][4]={};
  float dacc0=0.f, dacc1=0.f;
  float2 E[4]={ *(const float2*)(enp), *(const float2*)(enp+8),
                *(const float2*)(enp+16), *(const float2*)(enp+24) };
  uint32_t arow0=(uint32_t)(w*16+r0)*144u, arow1=arow0+8u*144u;

  for (int s=0;s<64;++s){
    int sn=(s+1<64)?(s+1):63;
    const float* ep=enp+sn*32;
    float2 nE0=*(const float2*)(ep),    nE1=*(const float2*)(ep+8);
    float2 nE2=*(const float2*)(ep+16), nE3=*(const float2*)(ep+24);

    CP_WAIT2();
    __syncthreads();
    if (s+3<64){
      uint32_t st=sb+(uint32_t)((s+3)&3)*STG_STRIDE;
#pragma unroll
      for (int q=0;q<4;++q) cp16cg(st+aoff[q], asrc[q]+(s+3)*32);
#pragma unroll
      for (int q=0;q<2;++q) cp16cg(st+boff[q], bsrc[q]+(size_t)(s+3)*32*128);
    }
    CP_COMMIT();

    uint32_t st=sb+(uint32_t)(s&3)*STG_STRIDE;
    char* stc=smc+(size_t)(st-sb);
#pragma unroll
    for (int h=0;h<2;++h){
      int col=(h*16+cq)*4;
      int2 A00=*(const int2*)(stc+arow0+col);
      int2 A01=*(const int2*)(stc+arow0+col+32);
      int2 A10=*(const int2*)(stc+arow1+col);
      int2 A11=*(const int2*)(stc+arow1+col+32);
      float2 E0=E[2*h], E1=E[2*h+1];
      float w00=A00.x?fmaxf(es0*E0.x,1.f):0.f, w01=A00.y?fmaxf(es0*E0.y,1.f):0.f;
      float w10=A10.x?fmaxf(es1*E0.x,1.f):0.f, w11=A10.y?fmaxf(es1*E0.y,1.f):0.f;
      float w02=A01.x?fmaxf(es0*E1.x,1.f):0.f, w03=A01.y?fmaxf(es0*E1.y,1.f):0.f;
      float w12=A11.x?fmaxf(es1*E1.x,1.f):0.f, w13=A11.y?fmaxf(es1*E1.y,1.f):0.f;
      dacc0 += (w00+w01)+(w02+w03);
      dacc1 += (w10+w11)+(w12+w13);
      uint32_t a0=packbf(w00,w01), a1=packbf(w10,w11), a2=packbf(w02,w03), a3=packbf(w12,w13);

      uint32_t bbase=st+(uint32_t)B_OFF+(uint32_t)(h*16*272)+lmoff;
#pragma unroll
      for (int nt2=0;nt2<8;++nt2){
        uint32_t q0,q1,q2,q3;
        ldsm4t(q0,q1,q2,q3, bbase+(uint32_t)nt2*32u);
        mma16816(acc[2*nt2][0],acc[2*nt2][1],acc[2*nt2][2],acc[2*nt2][3],       a0,a1,a2,a3, q0,q1);
        mma16816(acc[2*nt2+1][0],acc[2*nt2+1][1],acc[2*nt2+1][2],acc[2*nt2+1][3],a0,a1,a2,a3, q2,q3);
      }
    }
    E[0]=nE0; E[1]=nE1; E[2]=nE2; E[3]=nE3;
  }

  dacc0 += __shfl_xor_sync(0xffffffffu,dacc0,1);
  dacc0 += __shfl_xor_sync(0xffffffffu,dacc0,2);
  dacc1 += __shfl_xor_sync(0xffffffffu,dacc1,1);
  dacc1 += __shfl_xor_sync(0xffffffffu,dacc1,2);
  if ((lane&3)==0){
    g_den[blockIdx.x*128 + w*16 + r0]     = dacc0;
    g_den[blockIdx.x*128 + w*16 + r0 + 8] = dacc1;
  }
  float* gp0=g_part+((size_t)blockIdx.x*128 + w*16 + r0)*128 + cq;
  float* gp1=gp0 + (size_t)8*128;
#pragma unroll
  for (int nt=0;nt<16;++nt){
    *(float2*)(gp0+nt*8)=make_float2(acc[nt][0],acc[nt][1]);
    *(float2*)(gp1+nt*8)=make_float2(acc[nt][2],acc[nt][3]);
  }
}

// ---- epilogue: grid 1024, block 256 ----
__global__ void __launch_bounds__(256) k_epi(float* __restrict__ out){
  int t=blockIdx.x*256+threadIdx.x;
  int i=t>>5, fq=(t&31)*4;
  int it=i>>7, li=i&127;
  size_t pb=(((size_t)it*4)*128+li)*128+fq;
  float4 n0=*(const float4*)(g_part+pb);
  float4 n1=*(const float4*)(g_part+pb+128*128);
  float4 n2=*(const float4*)(g_part+pb+2*128*128);
  float4 n3=*(const float4*)(g_part+pb+3*128*128);
  int db=it*512+li;
  float den=g_den[db]+g_den[db+128]+g_den[db+256]+g_den[db+384];
  float4 hs=*(const float4*)(g_hs+(size_t)i*128+fq);
  float4 v;
  v.x=0.5f*hs.x+(n0.x+n1.x+n2.x+n3.x)/den;
  v.y=0.5f*hs.y+(n0.y+n1.y+n2.y+n3.y)/den;
  v.z=0.5f*hs.z+(n0.z+n1.z+n2.z+n3.z)/den;
  v.w=0.5f*hs.w+(n0.w+n1.w+n2.w+n3.w)/den;
  v.x = v.x>0.f ? v.x : expm1f(v.x);
  v.y = v.y>0.f ? v.y : expm1f(v.y);
  v.z = v.z>0.f ? v.z : expm1f(v.z);
  v.w = v.w>0.f ? v.w : expm1f(v.w);
  *(float4*)(out+(size_t)i*128+fq)=v;
}

extern "C" void kernel_launch(void* const* d_in, const int* in_sizes, int n_in,
                              void* d_out, int out_size){
  const float* X  =(const float*)d_in[0];
  const int*   adj=(const int*)d_in[1];
  const float* Ws =(const float*)d_in[2];
  const float* as_=(const float*)d_in[3];
  const float* Wn =(const float*)d_in[4];
  const float* an_=(const float*)d_in[5];
  cudaFuncSetAttribute(k_attn, cudaFuncAttributeMaxDynamicSharedMemorySize, SMEM_TOTAL);
  k_proj<<<dim3(64,2),256>>>(X, Ws, Wn, as_, an_);
  k_attn<<<256,256,SMEM_TOTAL>>>(adj);
  k_epi<<<1024,256>>>((float*)d_out);
}